// round 4
// baseline (speedup 1.0000x reference)
#include <cuda_runtime.h>

#define NB 256
#define NT 1024
#define NI 64
#define NH 25
#define NG 100   // 4*H
#define NO 64
#define NM (NB*NT)    // 262144 rows
#define NPAIR (NB/2)  // 128 batch pairs
#define HS_STRIDE 26  // padded row stride (in ull) for h pairs

// Precomputed input gates, layout [row][k][4] = (i_k, f_k, g_k, o_k): ~105 MB
static __device__ float g_gates[(size_t)NM * NG];
// Hidden states, batch-pair packed: g_hs[(pair*NT+t)*26 + k] = (h_b0[k], h_b1[k])
static __device__ unsigned long long g_hs[(size_t)NPAIR * NT * HS_STRIDE];

typedef unsigned long long ull;

__device__ __forceinline__ ull pack2(float a, float b){
    ull r; asm("mov.b64 %0,{%1,%2};" : "=l"(r) : "f"(a), "f"(b)); return r;
}
__device__ __forceinline__ float2 unpack2(ull v){
    float2 r; asm("mov.b64 {%0,%1},%2;" : "=f"(r.x), "=f"(r.y) : "l"(v)); return r;
}
__device__ __forceinline__ ull fma2(ull a, ull b, ull c){
    ull d; asm("fma.rn.f32x2 %0,%1,%2,%3;" : "=l"(d) : "l"(a), "l"(b), "l"(c)); return d;
}
__device__ __forceinline__ ull add2(ull a, ull b){
    ull d; asm("add.rn.f32x2 %0,%1,%2;" : "=l"(d) : "l"(a), "l"(b)); return d;
}
__device__ __forceinline__ float tanha(float x){
    float r; asm("tanh.approx.f32 %0,%1;" : "=f"(r) : "f"(x)); return r;
}
__device__ __forceinline__ float sig_t(float x){
    return fmaf(tanha(0.5f * x), 0.5f, 0.5f);
}

// ---------------------------------------------------------------------------
// Kernel 1: g_gates[row][k*4+{0..3}] = (i,f,g,o)_k pre-acts (unchanged)
// ---------------------------------------------------------------------------
__global__ void __launch_bounds__(256) gates_kernel(
    const float* __restrict__ x, const float* __restrict__ W_ih,
    const float* __restrict__ b_ih, const float* __restrict__ b_hh)
{
    __shared__ ull   xsd[100][33];
    __shared__ ull   wps[32][50];
    __shared__ float bsum[NG];

    const int tid   = threadIdx.x;          // 0..249
    const int pairc = tid % 10;
    const int rowt  = tid / 10;             // 0..24
    const int rowbase = blockIdx.x * 100;

    ull acc[4][5];
    #pragma unroll
    for (int r = 0; r < 4; r++)
        #pragma unroll
        for (int c = 0; c < 5; c++) acc[r][c] = 0ull;

    for (int pass = 0; pass < 2; pass++){
        const int ks = pass * 32;
        for (int idx = tid; idx < 100*32; idx += 250){
            int r = idx >> 5, k = idx & 31;
            int grow = rowbase + r;
            float v = (grow < NM) ? x[(size_t)grow * NI + ks + k] : 0.0f;
            xsd[r][k] = pack2(v, v);
        }
        for (int idx = tid; idx < 32*50; idx += 250){
            int k = idx / 50, c = idx % 50;
            int r0 = (c < 25) ? c      : 25 + c;
            int r1 = (c < 25) ? 25 + c : 50 + c;
            wps[k][c] = pack2(W_ih[r0 * NI + ks + k], W_ih[r1 * NI + ks + k]);
        }
        if (pass == 0)
            for (int j = tid; j < NG; j += 250) bsum[j] = b_ih[j] + b_hh[j];
        __syncthreads();

        #pragma unroll
        for (int k = 0; k < 32; k++){
            ull xd[4], wv[5];
            #pragma unroll
            for (int r = 0; r < 4; r++) xd[r] = xsd[rowt + 25*r][k];
            #pragma unroll
            for (int c = 0; c < 5; c++) wv[c] = wps[k][pairc + 10*c];
            #pragma unroll
            for (int r = 0; r < 4; r++)
                #pragma unroll
                for (int c = 0; c < 5; c++)
                    acc[r][c] = fma2(xd[r], wv[c], acc[r][c]);
        }
        __syncthreads();
    }

    #pragma unroll
    for (int r = 0; r < 4; r++){
        int grow = rowbase + rowt + 25*r;
        if (grow >= NM) continue;
        float* gp = g_gates + (size_t)grow * NG;
        #pragma unroll
        for (int cc = 0; cc < 5; cc++){
            int c = pairc + 10*cc;
            int base, r0, r1;
            if (c < 25){ base = 4*c;          r0 = c;      r1 = 25 + c; }
            else       { base = 4*(c-25) + 2; r0 = 25 + c; r1 = 50 + c; }
            float2 v = unpack2(acc[r][cc]);
            v.x += bsum[r0];
            v.y += bsum[r1];
            *reinterpret_cast<float2*>(gp + base) = v;
        }
    }
}

// ---------------------------------------------------------------------------
// Kernel 2: LSTM scan, 2 batches per warp, gates only (FC deferred).
// 128 blocks x 32 threads; warp w handles batches 2w, 2w+1.
// Lane k owns gate rows (i,f,g,o)_k and (c_k,h_k) for BOTH batches;
// shared weight registers; h broadcast via SHFL; h pairs stored to g_hs.
// ---------------------------------------------------------------------------
__global__ void __launch_bounds__(32, 1) lstm_scan(
    const float* __restrict__ W_hh)
{
    const int lane = threadIdx.x;
    const int pair = blockIdx.x;
    const int b0   = 2 * pair;
    const int k    = (lane < NH) ? lane : NH - 1;

    ull w_if[NH], w_go[NH];
    #pragma unroll
    for (int kk = 0; kk < NH; kk++){
        w_if[kk] = pack2(__ldg(W_hh + (     k) * NH + kk), __ldg(W_hh + (NH  + k) * NH + kk));
        w_go[kk] = pack2(__ldg(W_hh + (2*NH+k) * NH + kk), __ldg(W_hh + (3*NH+k) * NH + kk));
    }

    const float* gx0 = g_gates + (size_t)b0       * NT * NG + 4 * k;
    const float* gx1 = g_gates + (size_t)(b0 + 1) * NT * NG + 4 * k;
    ull*         hsp = g_hs    + (size_t)pair * NT * HS_STRIDE + k;

    float h0 = 0.0f, c0 = 0.0f, h1 = 0.0f, c1 = 0.0f;

    float4 p0[4], p1[4];
    #pragma unroll
    for (int d = 0; d < 4; d++){
        p0[d] = *reinterpret_cast<const float4*>(gx0 + d * NG);
        p1[d] = *reinterpret_cast<const float4*>(gx1 + d * NG);
    }

    for (int tb = 0; tb < NT; tb += 4){
        #pragma unroll
        for (int u = 0; u < 4; u++){
            const int t = tb + u;
            ull aif0_0 = pack2(p0[u].x, p0[u].y), aif1_0 = 0ull;
            ull ago0_0 = pack2(p0[u].z, p0[u].w), ago1_0 = 0ull;
            ull aif0_1 = pack2(p1[u].x, p1[u].y), aif1_1 = 0ull;
            ull ago0_1 = pack2(p1[u].z, p1[u].w), ago1_1 = 0ull;
            if (t + 4 < NT){
                p0[u] = *reinterpret_cast<const float4*>(gx0 + (size_t)(t + 4) * NG);
                p1[u] = *reinterpret_cast<const float4*>(gx1 + (size_t)(t + 4) * NG);
            }

            #pragma unroll
            for (int kk = 0; kk < NH; kk++){
                float hv0 = __shfl_sync(0xffffffffu, h0, kk);
                float hv1 = __shfl_sync(0xffffffffu, h1, kk);
                ull hd0 = pack2(hv0, hv0);
                ull hd1 = pack2(hv1, hv1);
                if (kk & 1){
                    aif1_0 = fma2(hd0, w_if[kk], aif1_0);
                    ago1_0 = fma2(hd0, w_go[kk], ago1_0);
                    aif1_1 = fma2(hd1, w_if[kk], aif1_1);
                    ago1_1 = fma2(hd1, w_go[kk], ago1_1);
                } else {
                    aif0_0 = fma2(hd0, w_if[kk], aif0_0);
                    ago0_0 = fma2(hd0, w_go[kk], ago0_0);
                    aif0_1 = fma2(hd1, w_if[kk], aif0_1);
                    ago0_1 = fma2(hd1, w_go[kk], ago0_1);
                }
            }

            float2 gif0 = unpack2(add2(aif0_0, aif1_0));
            float2 ggo0 = unpack2(add2(ago0_0, ago1_0));
            float2 gif1 = unpack2(add2(aif0_1, aif1_1));
            float2 ggo1 = unpack2(add2(ago0_1, ago1_1));

            float i0 = sig_t(gif0.x), f0 = sig_t(gif0.y);
            float g0 = tanha(ggo0.x), o0 = sig_t(ggo0.y);
            c0 = f0 * c0 + i0 * g0;
            h0 = o0 * tanha(c0);

            float i1 = sig_t(gif1.x), f1 = sig_t(gif1.y);
            float g1 = tanha(ggo1.x), o1 = sig_t(ggo1.y);
            c1 = f1 * c1 + i1 * g1;
            h1 = o1 * tanha(c1);

            if (lane < NH)
                hsp[(size_t)t * HS_STRIDE] = pack2(h0, h1);
        }
    }
}

// ---------------------------------------------------------------------------
// Kernel 3: FC head as batch-pair-packed f32x2 GEMM.
// M = 131072 pair-rows, K = 25, N = 64 outs. Block tile: 64 pair-rows x 64
// outs, 256 threads; thread = 4 pair-rows x 4 outs (16 ull accums).
// h pairs in smem; W_fc duplicated (w,w) in smem.
// ---------------------------------------------------------------------------
__global__ void __launch_bounds__(256) fc_kernel(
    const float* __restrict__ W_fc, const float* __restrict__ b_fc,
    float* __restrict__ out)
{
    __shared__ ull hsm[64][HS_STRIDE];   // 64 pair-rows x padded 26
    __shared__ ull wsd[NH][NO];          // (w,w) duplicated
    __shared__ ull bsd[NO];

    const int tid = threadIdx.x;
    const size_t prbase = (size_t)blockIdx.x * 64;

    // stage h tile (copy 64*26 ull straight, preserves pad)
    {
        const ull* src = g_hs + prbase * HS_STRIDE;
        for (int idx = tid; idx < 64 * HS_STRIDE; idx += 256)
            hsm[idx / HS_STRIDE][idx % HS_STRIDE] = src[idx];
    }
    for (int idx = tid; idx < NH * NO; idx += 256){
        int kk = idx / NO, j = idx % NO;
        float w = W_fc[j * NH + kk];
        wsd[kk][j] = pack2(w, w);
    }
    if (tid < NO){
        float bv = b_fc[tid];
        bsd[tid] = pack2(bv, bv);
    }
    __syncthreads();

    const int jc = tid & 15;         // out group: 4 outs j0 = 4*jc
    const int rc = tid >> 4;         // row group: 4 pair-rows r0 = 4*rc
    const int j0 = 4 * jc;
    const int r0 = 4 * rc;

    ull acc[4][4];
    #pragma unroll
    for (int r = 0; r < 4; r++)
        #pragma unroll
        for (int j = 0; j < 4; j++) acc[r][j] = bsd[j0 + j];

    #pragma unroll
    for (int kk = 0; kk < NH; kk++){
        ull hv[4], wv[4];
        #pragma unroll
        for (int r = 0; r < 4; r++) hv[r] = hsm[r0 + r][kk];
        #pragma unroll
        for (int j = 0; j < 4; j++) wv[j] = wsd[kk][j0 + j];
        #pragma unroll
        for (int r = 0; r < 4; r++)
            #pragma unroll
            for (int j = 0; j < 4; j++)
                acc[r][j] = fma2(hv[r], wv[j], acc[r][j]);
    }

    #pragma unroll
    for (int r = 0; r < 4; r++){
        size_t pr   = prbase + r0 + r;         // pair-row = pair*NT + t
        size_t pairi = pr / NT;
        size_t t     = pr - pairi * NT;
        float* ob0 = out + ((2*pairi    ) * NT + t) * NO + j0;
        float* ob1 = out + ((2*pairi + 1) * NT + t) * NO + j0;
        float4 v0, v1;
        float2 e0 = unpack2(acc[r][0]), e1 = unpack2(acc[r][1]);
        float2 e2 = unpack2(acc[r][2]), e3 = unpack2(acc[r][3]);
        v0.x = e0.x; v0.y = e1.x; v0.z = e2.x; v0.w = e3.x;
        v1.x = e0.y; v1.y = e1.y; v1.z = e2.y; v1.w = e3.y;
        *reinterpret_cast<float4*>(ob0) = v0;
        *reinterpret_cast<float4*>(ob1) = v1;
    }
}

extern "C" void kernel_launch(void* const* d_in, const int* in_sizes, int n_in,
                              void* d_out, int out_size)
{
    (void)in_sizes; (void)n_in; (void)out_size;
    const float* x    = (const float*)d_in[0];
    const float* W_ih = (const float*)d_in[1];
    const float* W_hh = (const float*)d_in[2];
    const float* b_ih = (const float*)d_in[3];
    const float* b_hh = (const float*)d_in[4];
    const float* W_fc = (const float*)d_in[5];
    const float* b_fc = (const float*)d_in[6];
    float* out = (float*)d_out;

    gates_kernel<<<(NM + 99) / 100, 250>>>(x, W_ih, b_ih, b_hh);
    lstm_scan<<<NPAIR, 32>>>(W_hh);
    fc_kernel<<<(NPAIR * NT) / 64, 256>>>(W_fc, b_fc, out);
}